// round 15
// baseline (speedup 1.0000x reference)
#include <cuda_runtime.h>
#include <cuda_bf16.h>
#include <cstdint>

typedef unsigned long long ull;

// ===================== constants =====================
#define TDL  128
#define AST  144
#define R_A  0
#define R_B  18432            // 128*144
#define STAGE2 27648          // A(18432) + B(9216)
#define SMEM_MMA (2 * STAGE2) // 55296 -> 3 blocks/SM
#define HMAX 64
#define LMAX 16384
#define PRMAX 4096
#define LSPLIT 2048

__device__ float    g_sf[3][HMAX * LMAX];          // full-size partials (pass0, k=1..3)
__device__ float    g_sh[8][HMAX * LSPLIT];        // heavy partials (hl,lh x k)
__device__ uint32_t g_whi32[HMAX * PRMAX];
__device__ uint32_t g_wlo32[HMAX * PRMAX];

__device__ __forceinline__ uint32_t smem_u32(const void* p) {
    uint32_t a;
    asm("{ .reg .u64 t; cvta.to.shared.u64 t, %1; cvt.u32.u64 %0, t; }"
        : "=r"(a) : "l"(p));
    return a;
}
__device__ __forceinline__ uint32_t prmt_(uint32_t a, uint32_t b, uint32_t sel) {
    uint32_t d;
    asm("prmt.b32 %0, %1, %2, %3;" : "=r"(d) : "r"(a), "r"(b), "r"(sel));
    return d;
}
__device__ __forceinline__ uint32_t cvt_bf16x2(float hi_elem, float lo_elem) {
    uint32_t d;
    asm("cvt.rn.bf16x2.f32 %0, %1, %2;" : "=r"(d) : "f"(hi_elem), "f"(lo_elem));
    return d;
}
__device__ __forceinline__ void ldm_x4(uint32_t* r, uint32_t addr) {
    asm volatile("ldmatrix.sync.aligned.m8n8.x4.shared.b16 {%0,%1,%2,%3}, [%4];"
                 : "=r"(r[0]), "=r"(r[1]), "=r"(r[2]), "=r"(r[3]) : "r"(addr));
}
__device__ __forceinline__ void mma_bf16(float* c, const uint32_t* a,
                                         uint32_t b0, uint32_t b1) {
    asm volatile(
        "mma.sync.aligned.m16n8k16.row.col.f32.bf16.bf16.f32 "
        "{%0,%1,%2,%3}, {%4,%5,%6,%7}, {%8,%9}, {%0,%1,%2,%3};"
        : "+f"(c[0]), "+f"(c[1]), "+f"(c[2]), "+f"(c[3])
        : "r"(a[0]), "r"(a[1]), "r"(a[2]), "r"(a[3]), "r"(b0), "r"(b1));
}

// ===================== W pre-split =====================
__global__ void w_split_kernel(const float* __restrict__ W, int P, int H, int Pr)
{
    int total = HMAX * Pr;
    for (int idx = blockIdx.x * blockDim.x + threadIdx.x; idx < total;
         idx += gridDim.x * blockDim.x) {
        int h = idx / Pr, p = idx % Pr;
        float wr = 0.f, wi = 0.f;
        if (h < H && p < P) {
            float2 w = *(const float2*)(W + ((size_t)h * P + p) * 2);
            wr = w.x; wi = -w.y;
        }
        uint32_t ur = __float_as_uint(wr), ui = __float_as_uint(wi);
        float hr = __uint_as_float(ur & 0xffff0000u);
        float hs = __uint_as_float(ui & 0xffff0000u);
        g_whi32[h * Pr + p] = prmt_(ur, ui, 0x7632);
        g_wlo32[h * Pr + p] = cvt_bf16x2(wi - hs, wr - hr);
    }
}

// ===================== A' chunk synthesis (prologue) =====================
__device__ __forceinline__ void synth_chunk1(char* stage, const float* __restrict__ A,
                                             int p0, int P, int l0, int lane, int seg,
                                             bool wantlo)
{
    char* aS = stage + R_A;
    int p = p0 + lane;
    float vr = 0.f, vi = 0.f, axr = 0.f, axi = 0.f;
    if (p < P) {
        float2 a = *(const float2*)(A + 2 * p);
        axr = a.x; axi = a.y;
        float lr = 0.5f * logf(a.x * a.x + a.y * a.y);
        float th = atan2f(a.y, a.x);
        float e = (float)(l0 + seg * 16);
        float mag = expf(lr * e);
        float sp, cp;
        sincosf(th * e, &sp, &cp);
        vr = mag * cp; vi = mag * sp;
    }
#pragma unroll
    for (int j = 0; j < 16; ++j) {
        int l = seg * 16 + j;
        uint32_t ur = __float_as_uint(vr), ui = __float_as_uint(vi);
        uint32_t val;
        if (wantlo) {
            float hr = __uint_as_float(ur & 0xffff0000u);
            float hs = __uint_as_float(ui & 0xffff0000u);
            val = cvt_bf16x2(vi - hs, vr - hr);
        } else {
            val = prmt_(ur, ui, 0x7632);
        }
        *(uint32_t*)(aS + l * AST + 4 * lane) = val;
        float nvr = vr * axr - vi * axi;
        float nvi = vr * axi + vi * axr;
        vr = nvr; vi = nvi;
    }
}

// ===================== main HMMA kernel: uniform single-pass jobs =====================
extern __shared__ char smem_raw[];

__global__ void __launch_bounds__(256, 3)
mv_mma5_kernel(const float* __restrict__ A, float* __restrict__ out,
               int P, int H, int L, int Pr, long long out_cap, int tiles)
{
    char* smem = smem_raw;
    const uint32_t sb = smem_u32(smem);
    const int tid  = threadIdx.x;
    const int lane = tid & 31;
    const int wid  = tid >> 5;
    const int wm   = wid & 3;
    const int wn   = wid >> 2;

    // ---- decode job ----
    const int jid = blockIdx.x;
    const int np0 = tiles * 4;
    int tile, k, pass;
    float* dst; int ldst; long long cap;
    if (jid < np0) {
        tile = jid >> 2; k = jid & 3; pass = 0;
        if (k == 0) { dst = out; cap = out_cap; }
        else        { dst = g_sf[k - 1]; cap = (long long)HMAX * LMAX; }
        ldst = L;
    } else {
        int e = jid - np0;
        tile = e >> 3;
        int sub = e & 7;              // (pass-1)*4 + k
        pass = 1 + (sub >> 2); k = sub & 3;
        dst = g_sh[sub]; ldst = LSPLIT; cap = (long long)HMAX * LSPLIT;
    }
    const int l0 = tile * TDL;
    const bool wantlo = (pass == 2);
    const uint32_t* wsrc = (pass == 1) ? g_wlo32 : g_whi32;

    const int nch_tot = Pr / 32;
    const int cpb = (nch_tot + 3) / 4;
    const int cB = k * cpb;
    const int cE = min(nch_tot, cB + cpb);

    const uint32_t aRel = (uint32_t)((wm * 32 + (lane & 15)) * AST + ((lane >> 4) << 4));
    const int bRow = wn * 32 + ((lane >> 4) << 3) + (lane & 7);
    const uint32_t bRel = (uint32_t)(R_B + bRow * AST + ((lane & 8) ? 16 : 0));

    float acc[2][4][4];
#pragma unroll
    for (int mi = 0; mi < 2; ++mi)
#pragma unroll
        for (int j = 0; j < 4; ++j)
#pragma unroll
            for (int q = 0; q < 4; ++q) acc[mi][j][q] = 0.f;

    // ---- prologue: fill stage 0 with chunk cB ----
    if (cB < cE) {
#pragma unroll
        for (int t = 0; t < 2; ++t) {
            int idx = tid + 256 * t;
            int h = idx >> 3, q = idx & 7;
            uint4 v = ((const uint4*)(wsrc + h * Pr + cB * 32))[q];
            *(uint4*)(smem + R_B + h * AST + q * 16) = v;
        }
        synth_chunk1(smem, A, cB * 32, P, l0, lane, wid, wantlo);
    }
    __syncthreads();

    // ---- main loop: MMA(cur) interleaved with synth(next) ----
    for (int c = cB; c < cE; ++c) {
        const int st = (c - cB) & 1;
        char* nxt = smem + (st ^ 1) * STAGE2;
        const bool havenext = (c + 1 < cE);

        uint4 wv[2];
        if (havenext) {
#pragma unroll
            for (int t = 0; t < 2; ++t) {
                int idx = tid + 256 * t;
                int h = idx >> 3, q = idx & 7;
                wv[t] = ((const uint4*)(wsrc + h * Pr + (c + 1) * 32))[q];
            }
        }

        const uint32_t sbase = sb + st * STAGE2;
        const uint32_t aB = sbase + R_A + aRel;
        const uint32_t bB = sbase + bRel;

        float vr = 0.f, vi = 0.f, axr = 0.f, axi = 0.f;
        char* aN = nxt + R_A;
        const int p_n = (c + 1) * 32 + lane;

#pragma unroll
        for (int ks = 0; ks < 4; ++ks) {
            const uint32_t kb = ks * 32;
            uint32_t a0[4], a1[4], b[8];
            ldm_x4(a0, aB + kb);
            ldm_x4(a1, aB + 16 * AST + kb);
            ldm_x4(b,     bB + kb);
            ldm_x4(b + 4, bB + 16 * AST + kb);
#pragma unroll
            for (int j = 0; j < 4; ++j) {
                mma_bf16(acc[0][j], a0, b[2 * j], b[2 * j + 1]);
                mma_bf16(acc[1][j], a1, b[2 * j], b[2 * j + 1]);
            }

            if (havenext) {
                if (ks == 0) {
                    if (p_n < P) {
                        float2 a = *(const float2*)(A + 2 * p_n);
                        axr = a.x; axi = a.y;
                        float lr = 0.5f * logf(a.x * a.x + a.y * a.y);
                        float th = atan2f(a.y, a.x);
                        float e = (float)(l0 + wid * 16);
                        float mag = expf(lr * e);
                        float sp, cp;
                        sincosf(th * e, &sp, &cp);
                        vr = mag * cp; vi = mag * sp;
                    } else { vr = vi = axr = axi = 0.f; }
                }
#pragma unroll
                for (int j = 0; j < 4; ++j) {
                    int l = wid * 16 + ks * 4 + j;
                    uint32_t ur = __float_as_uint(vr), ui = __float_as_uint(vi);
                    uint32_t val;
                    if (wantlo) {
                        float hr = __uint_as_float(ur & 0xffff0000u);
                        float hs = __uint_as_float(ui & 0xffff0000u);
                        val = cvt_bf16x2(vi - hs, vr - hr);
                    } else {
                        val = prmt_(ur, ui, 0x7632);
                    }
                    *(uint32_t*)(aN + l * AST + 4 * lane) = val;
                    float nvr = vr * axr - vi * axi;
                    float nvi = vr * axi + vi * axr;
                    vr = nvr; vi = nvi;
                }
                if (ks < 2) {
                    int idx = tid + 256 * ks;
                    int h = idx >> 3, q = idx & 7;
                    *(uint4*)(nxt + R_B + h * AST + q * 16) = wv[ks];
                }
            }
        }
        __syncthreads();
    }

    // ---- epilogue ----
    const int trow  = lane >> 2;
    const int tcol2 = (lane & 3) * 2;
#pragma unroll
    for (int mi = 0; mi < 2; ++mi) {
        int lA = l0 + wm * 32 + mi * 16 + trow;
        int lB = lA + 8;
#pragma unroll
        for (int j = 0; j < 4; ++j) {
            int h0 = wn * 32 + j * 8 + tcol2;
            int h1 = h0 + 1;
            if (h0 < H) {
                if (lA < ldst) { long long f = (long long)h0 * ldst + lA; if (f < cap) dst[f] = acc[mi][j][0]; }
                if (lB < ldst) { long long f = (long long)h0 * ldst + lB; if (f < cap) dst[f] = acc[mi][j][2]; }
            }
            if (h1 < H) {
                if (lA < ldst) { long long f = (long long)h1 * ldst + lA; if (f < cap) dst[f] = acc[mi][j][1]; }
                if (lB < ldst) { long long f = (long long)h1 * ldst + lB; if (f < cap) dst[f] = acc[mi][j][3]; }
            }
        }
    }
}

// out += sf1+sf2+sf3 (all); heavy cols also += 8 heavy partials
__global__ void combine3_kernel(float* __restrict__ out, long long n4, int L4)
{
    const float4* s1 = (const float4*)g_sf[0];
    const float4* s2 = (const float4*)g_sf[1];
    const float4* s3 = (const float4*)g_sf[2];
    const float4* sh = (const float4*)g_sh;
    float4* o4 = (float4*)out;
    const int Ls4 = LSPLIT / 4;
    const int hstr = HMAX * Ls4;       // float4 stride per heavy buffer
    long long i = (long long)blockIdx.x * blockDim.x + threadIdx.x;
    long long stride = (long long)gridDim.x * blockDim.x;
    for (; i < n4; i += stride) {
        int h  = (int)(i / L4);
        int lq = (int)(i - (long long)h * L4);
        float4 a = o4[i], b = s1[i], c = s2[i], d = s3[i];
        a.x += b.x + c.x + d.x; a.y += b.y + c.y + d.y;
        a.z += b.z + c.z + d.z; a.w += b.w + c.w + d.w;
        if (lq < Ls4) {
            int hb = h * Ls4 + lq;
#pragma unroll
            for (int bx = 0; bx < 8; ++bx) {
                float4 e = sh[bx * hstr + hb];
                a.x += e.x; a.y += e.y; a.z += e.z; a.w += e.w;
            }
        }
        o4[i] = a;
    }
}

// ================= SIMT fallback (R9, known-good, non-conforming shapes) =================
#define KC 32
#define TL 128
#define VSTRIDE 130
#define FB_NT 256

__device__ __forceinline__ ull pk2(float lo, float hi) {
    ull r; asm("mov.b64 %0, {%1, %2};" : "=l"(r) : "f"(lo), "f"(hi)); return r;
}
__device__ __forceinline__ void upk2(ull v, float& lo, float& hi) {
    asm("mov.b64 {%0, %1}, %2;" : "=f"(lo), "=f"(hi) : "l"(v));
}
__device__ __forceinline__ void fma2(ull& d, ull a, ull b) {
    asm("fma.rn.f32x2 %0, %1, %2, %3;" : "=l"(d) : "l"(a), "l"(b), "l"(d));
}
#define V_BYTES   (KC * VSTRIDE * 8)
#define WP_BYTES  ((HMAX / 2) * KC * 16)
#define FB_SMEM_FIXED (V_BYTES + WP_BYTES)

__global__ void __launch_bounds__(FB_NT, 2)
mv_gemm_kernel(const float* __restrict__ A, const float* __restrict__ W,
               float* __restrict__ out, int P, int H, int L,
               long long out_cap)
{
    extern __shared__ char smem[];
    float2* Vc = (float2*)smem;
    float4* Wp = (float4*)(smem + V_BYTES);
    float2* Ls = (float2*)(smem + FB_SMEM_FIXED);

    const int tid  = threadIdx.x;
    const int l0   = blockIdx.x * TL;
    const int lane = tid & 31;
    const int wid  = tid >> 5;
    const int wg   = wid & 3;
    const int cg   = wid >> 2;
    const int c0   = cg * 64 + lane;
    const int c1   = c0 + 32;

    for (int p = tid; p < P; p += FB_NT) {
        float ar = A[2 * p], ai = A[2 * p + 1];
        Ls[p] = make_float2(0.5f * logf(ar * ar + ai * ai), atan2f(ai, ar));
    }
    __syncthreads();

    ull acc[8][2];
#pragma unroll
    for (int s = 0; s < 8; ++s) { acc[s][0] = 0ull; acc[s][1] = 0ull; }

    const int nchunks = (P + KC - 1) / KC;
#pragma unroll 1
    for (int c = 0; c < nchunks; ++c) {
        const int p0 = c * KC;
#pragma unroll
        for (int i = 0; i < (KC * HMAX / 2) / FB_NT; ++i) {
            int idx = tid + FB_NT * i;
            int hp = idx >> 5, pl = idx & 31, p = p0 + pl;
            int h0 = 2 * hp, h1 = 2 * hp + 1;
            float wr0 = 0.f, wi0 = 0.f, wr1 = 0.f, wi1 = 0.f;
            if (p < P) {
                if (h0 < H) { float2 w = *(const float2*)(W + ((size_t)h0 * P + p) * 2); wr0 = w.x; wi0 = w.y; }
                if (h1 < H) { float2 w = *(const float2*)(W + ((size_t)h1 * P + p) * 2); wr1 = w.x; wi1 = w.y; }
            }
            Wp[hp * KC + pl] = make_float4(wr0, wr1, -wi0, -wi1);
        }
#pragma unroll
        for (int i = 0; i < 2; ++i) {
            int slot = tid + FB_NT * i;
            int fseg = slot >> 5, flane = slot & 31;
            const int p = p0 + flane;
            float vr = 0.f, vi = 0.f, axr = 0.f, axi = 0.f;
            if (p < P) {
                float2 lt = Ls[p];
                axr = A[2 * p]; axi = A[2 * p + 1];
                const float e = (float)(l0 + fseg * 8);
                float mag = expf(lt.x * e);
                float sp, cp; sincosf(lt.y * e, &sp, &cp);
                vr = mag * cp; vi = mag * sp;
            }
#pragma unroll
            for (int jp = 0; jp < 4; ++jp) {
                float vr1 = vr * axr - vi * axi;
                float vi1 = vr * axi + vi * axr;
                *(float4*)&Vc[flane * VSTRIDE + fseg * 8 + 2 * jp] = make_float4(vr, vi, vr1, vi1);
                vr = vr1 * axr - vi1 * axi;
                vi = vr1 * axi + vi1 * axr;
            }
        }
        __syncthreads();
#pragma unroll 4
        for (int kk = 0; kk < KC; ++kk) {
            float2 a0 = Vc[kk * VSTRIDE + c0];
            float2 a1 = Vc[kk * VSTRIDE + c1];
            ull vrr0 = pk2(a0.x, a0.x), vii0 = pk2(a0.y, a0.y);
            ull vrr1 = pk2(a1.x, a1.x), vii1 = pk2(a1.y, a1.y);
#pragma unroll
            for (int s = 0; s < 8; ++s) {
                ulonglong2 wp = *(ulonglong2*)&Wp[(wg * 8 + s) * KC + kk];
                fma2(acc[s][0], wp.x, vrr0);
                fma2(acc[s][0], wp.y, vii0);
                fma2(acc[s][1], wp.x, vrr1);
                fma2(acc[s][1], wp.y, vii1);
            }
        }
        __syncthreads();
    }
#pragma unroll
    for (int s = 0; s < 8; ++s) {
        int hp = wg * 8 + s;
        int h0 = 2 * hp, h1 = 2 * hp + 1;
#pragma unroll
        for (int r = 0; r < 2; ++r) {
            int col = (r == 0) ? c0 : c1;
            int l = l0 + col;
            if (l < L) {
                float e0, e1; upk2(acc[s][r], e0, e1);
                long long f0 = (long long)h0 * L + l;
                long long f1 = (long long)h1 * L + l;
                if (h0 < H && f0 < out_cap) out[f0] = e0;
                if (h1 < H && f1 < out_cap) out[f1] = e1;
            }
        }
    }
}

// ======================== launch ========================
extern "C" void kernel_launch(void* const* d_in, const int* in_sizes, int n_in,
                              void* d_out, int out_size) {
    int a_idx = -1, w_idx = -1;
    for (int i = 0; i < n_in; ++i) {
        if (in_sizes[i] <= 1) continue;
        if (a_idx < 0) { a_idx = i; }
        else if (w_idx < 0) {
            w_idx = i;
            if (in_sizes[a_idx] > in_sizes[w_idx]) { int t = a_idx; a_idx = w_idx; w_idx = t; }
        }
    }
    if (a_idx < 0 || w_idx < 0) return;

    const float* A = (const float*)d_in[a_idx];
    const float* W = (const float*)d_in[w_idx];
    float* out = (float*)d_out;

    int P = in_sizes[a_idx] / 2;
    int H = in_sizes[w_idx] / in_sizes[a_idx];
    if (P <= 0 || H <= 0) return;
    int L = out_size / H;
    if (L <= 0) return;

    int Pr = ((P + 31) / 32) * 32;
    bool conforming = (H <= HMAX) && (Pr <= PRMAX) &&
                      (L % TDL == 0) && (L >= LSPLIT) &&
                      ((long long)H * L <= (long long)HMAX * LMAX) &&
                      ((out_size & 3) == 0);

    if (conforming) {
        w_split_kernel<<<512, 256>>>(W, P, H, Pr);

        cudaFuncSetAttribute(mv_mma5_kernel,
                             cudaFuncAttributeMaxDynamicSharedMemorySize, SMEM_MMA);
        int tiles = L / TDL;
        int nheavy = LSPLIT / TDL;          // 16
        int njobs = tiles * 4 + nheavy * 8; // 640 for the bench shape
        mv_mma5_kernel<<<njobs, 256, SMEM_MMA>>>(A, out, P, H, L, Pr,
                                                 (long long)out_size, tiles);

        long long n4 = (long long)out_size / 4;
        int L4 = L / 4;
        int cblocks = (int)min((long long)2048, (n4 + 255) / 256);
        combine3_kernel<<<cblocks, 256>>>(out, n4, L4);
    } else {
        size_t smem = FB_SMEM_FIXED + (size_t)P * 8;
        cudaFuncSetAttribute(mv_gemm_kernel,
                             cudaFuncAttributeMaxDynamicSharedMemorySize, (int)smem);
        int grid = (L + TL - 1) / TL;
        mv_gemm_kernel<<<grid, FB_NT, smem>>>(A, W, out, P, H, L, (long long)out_size);
    }
}